// round 3
// baseline (speedup 1.0000x reference)
#include <cuda_runtime.h>
#include <math.h>

// ---------------------------------------------------------------------------
// CrossScaleNonLocalAttention  (B=8, H=W=64, C=64, CI=32, SCALE=4, PATCH=3)
//
// Restructured math:
//   theta = prelu(x @ tw + tb)                       [B,64,64,32] (padded 66x66)
//   phi   = prelu(down4(x) @ pw + pb)                [B,16,16,32] (padded 18x18)
//   phin  = phi 3x3 patches, L2-normalized per n     stored [B, 288, 256] (K-major)
//   scores[b,m,n] = theta_patch[m] . phin[n]  -> softmax(*10)   [B,4096,256]
//   A'[a,b,mh,mw] = sum_{di,dj in {-1,0,1}} attn[a-di,b-dj,mh-di,mw-dj]
//   y[4a+r,4b+q,co] = (1/6) * sum_{mh,mw} A'[(a,b),(mh,mw)] * g[4mh+r,4mw+q,co]
// The boundary taps of the deconv hit g's zero padding exactly, so the final
// stage is a clean GEMM per batch: [4096 x 256] @ [256 x 1024].
// ---------------------------------------------------------------------------

#define NB 8

__device__ float d_theta[NB][66][66][32];   // zero-padded border (never written)
__device__ float d_phi[NB][18][18][32];     // zero-padded border
__device__ float d_phin[NB][288][256];      // [k][n]  K-major for GEMM B
__device__ float d_G[NB][256][1024];        // G[(mh,mw)][(r*4+q)*64+co] = g(4mh+r,4mw+q,co)
__device__ float d_attn[NB][4096][256];
__device__ float d_Ap[NB][4096][256];

// ---------------------------------------------------------------------------
// Kernel 1: theta (64->32) and g (64->64) 1x1 conv + PReLU, fused.
// One block per (b, h) row of 64 pixels.
// ---------------------------------------------------------------------------
__global__ __launch_bounds__(256) void k_theta_g(
    const float* __restrict__ x,
    const float* __restrict__ tw, const float* __restrict__ tb, const float* __restrict__ ta,
    const float* __restrict__ gw, const float* __restrict__ gb, const float* __restrict__ ga)
{
    int b = blockIdx.x >> 6, h = blockIdx.x & 63;
    __shared__ float xs[64 * 64];
    __shared__ float tws[64 * 32];
    __shared__ float gws[64 * 64];
    __shared__ float tbs[32], tas[32], gbs[64], gas[64];
    int t = threadIdx.x;
    for (int i = t; i < 64 * 32; i += 256) tws[i] = tw[i];
    for (int i = t; i < 64 * 64; i += 256) gws[i] = gw[i];
    if (t < 32) { tbs[t] = tb[t]; tas[t] = ta[t]; }
    if (t < 64) { gbs[t] = gb[t]; gas[t] = ga[t]; }
    const float* xrow = x + ((size_t)(b * 4096 + h * 64)) * 64;
    for (int i = t * 4; i < 4096; i += 1024)
        *(float4*)&xs[i] = *(const float4*)&xrow[i];
    __syncthreads();

    int px = t >> 2, l4 = t & 3;
    // theta: 8 outputs per thread
    {
        float acc[8];
        int d0 = l4 * 8;
        #pragma unroll
        for (int j = 0; j < 8; j++) acc[j] = tbs[d0 + j];
        #pragma unroll 8
        for (int c = 0; c < 64; c++) {
            float xv = xs[px * 64 + c];
            #pragma unroll
            for (int j = 0; j < 8; j++) acc[j] = fmaf(xv, tws[c * 32 + d0 + j], acc[j]);
        }
        float* o = &d_theta[b][h + 1][px + 1][d0];
        #pragma unroll
        for (int j = 0; j < 8; j++) { float v = acc[j]; o[j] = v >= 0.f ? v : tas[d0 + j] * v; }
    }
    // g: 16 outputs per thread, stored directly in final-GEMM B layout
    {
        float acc[16];
        int d0 = l4 * 16;
        #pragma unroll
        for (int j = 0; j < 16; j++) acc[j] = gbs[d0 + j];
        #pragma unroll 8
        for (int c = 0; c < 64; c++) {
            float xv = xs[px * 64 + c];
            #pragma unroll
            for (int j = 0; j < 16; j++) acc[j] = fmaf(xv, gws[c * 64 + d0 + j], acc[j]);
        }
        int mh = h >> 2, r = h & 3, mw = px >> 2, q = px & 3;
        float* o = &d_G[b][mh * 16 + mw][((r * 4 + q) << 6) + d0];
        #pragma unroll
        for (int j = 0; j < 16; j++) { float v = acc[j]; o[j] = v >= 0.f ? v : gas[d0 + j] * v; }
    }
}

// ---------------------------------------------------------------------------
// Kernel 2: phi = prelu(conv1x1(bilinear_down4(x))).
// bilinear (align half-pixel, antialias=False, scale 1/4):
//   src coord = 4*i + 1.5  -> 0.5*(x[4i+1] + x[4i+2]) per axis.
// One block per batch, one thread per (nh, nw).
// ---------------------------------------------------------------------------
__global__ __launch_bounds__(256) void k_phi(
    const float* __restrict__ x,
    const float* __restrict__ pw, const float* __restrict__ pb, const float* __restrict__ pa)
{
    int b = blockIdx.x;
    int t = threadIdx.x;
    __shared__ float pws[64 * 32];
    __shared__ float pbs[32], pas[32];
    for (int i = t; i < 64 * 32; i += 256) pws[i] = pw[i];
    if (t < 32) { pbs[t] = pb[t]; pas[t] = pa[t]; }
    __syncthreads();
    int nh = t >> 4, nw = t & 15;
    const float* xb = x + (size_t)b * 4096 * 64;
    const float* r0 = xb + ((4 * nh + 1) * 64 + (4 * nw + 1)) * 64;
    const float* r1 = xb + ((4 * nh + 2) * 64 + (4 * nw + 1)) * 64;
    float acc[32];
    #pragma unroll
    for (int d = 0; d < 32; d++) acc[d] = pbs[d];
    for (int c = 0; c < 64; c++) {
        float xv = 0.25f * (r0[c] + r0[64 + c] + r1[c] + r1[64 + c]);
        #pragma unroll
        for (int d = 0; d < 32; d++) acc[d] = fmaf(xv, pws[c * 32 + d], acc[d]);
    }
    float* o = &d_phi[b][nh + 1][nw + 1][0];
    #pragma unroll
    for (int d = 0; d < 32; d++) { float v = acc[d]; o[d] = v >= 0.f ? v : pas[d] * v; }
}

// ---------------------------------------------------------------------------
// Kernel 3: per-n patch L2 norm; write normalized patch rows K-major.
// One warp per (b, n). k = (p*3+q)*32 + c.
// ---------------------------------------------------------------------------
__global__ __launch_bounds__(256) void k_phin()
{
    int gwid = (blockIdx.x * 256 + threadIdx.x) >> 5;
    int lane = threadIdx.x & 31;
    if (gwid >= NB * 256) return;
    int b = gwid >> 8, n = gwid & 255;
    int nh = n >> 4, nw = n & 15;
    float v[9], ss = 0.f;
    #pragma unroll
    for (int i = 0; i < 9; i++) {
        v[i] = d_phi[b][nh + i / 3][nw + i % 3][lane];
        ss = fmaf(v[i], v[i], ss);
    }
    #pragma unroll
    for (int o = 16; o > 0; o >>= 1) ss += __shfl_xor_sync(0xffffffffu, ss, o);
    float rn = 1.0f / fmaxf(sqrtf(ss), 1e-6f);
    #pragma unroll
    for (int i = 0; i < 9; i++) d_phin[b][i * 32 + lane][n] = v[i] * rn;
}

// ---------------------------------------------------------------------------
// Kernel 4: scores GEMM (M=4096, N=256, K=288) + fused softmax(*10).
// Block: 256 threads, tile 32 rows x 256 cols. Warp w owns rows 4w..4w+3;
// lane holds cols {lane + 32*j}. K chunks of 16 = one (p,q) half-channel group.
// ---------------------------------------------------------------------------
__global__ __launch_bounds__(256) void k_scores()
{
    int b = blockIdx.y;
    int m0 = blockIdx.x * 32;
    int h = m0 >> 6, w0 = m0 & 63;
    __shared__ float Asm[32][17];
    __shared__ float Bsm[16][256];
    int t = threadIdx.x;
    int rg = t >> 5, lane = t & 31;
    float acc[4][8];
    #pragma unroll
    for (int i = 0; i < 4; i++)
        #pragma unroll
        for (int j = 0; j < 8; j++) acc[i][j] = 0.f;

    int kk_l = t & 15, wl0 = t >> 4;
    for (int chunk = 0; chunk < 18; chunk++) {
        int pq = chunk >> 1;
        int c0 = (chunk & 1) << 4;
        int p = pq / 3, q = pq - 3 * p;
        // A tile: theta_patch rows (coalesced 64B runs)
        Asm[wl0][kk_l]      = d_theta[b][h + p][w0 + wl0 + q][c0 + kk_l];
        Asm[wl0 + 16][kk_l] = d_theta[b][h + p][w0 + wl0 + 16 + q][c0 + kk_l];
        // B tile: phin K-major rows (fully coalesced)
        #pragma unroll
        for (int kk = 0; kk < 16; kk++)
            Bsm[kk][t] = d_phin[b][chunk * 16 + kk][t];
        __syncthreads();
        #pragma unroll
        for (int kk = 0; kk < 16; kk++) {
            float av[4], bv[8];
            #pragma unroll
            for (int i = 0; i < 4; i++) av[i] = Asm[rg * 4 + i][kk];
            #pragma unroll
            for (int j = 0; j < 8; j++) bv[j] = Bsm[kk][lane + 32 * j];
            #pragma unroll
            for (int i = 0; i < 4; i++)
                #pragma unroll
                for (int j = 0; j < 8; j++)
                    acc[i][j] = fmaf(av[i], bv[j], acc[i][j]);
        }
        __syncthreads();
    }
    // fused softmax over the 256 cols of each row (full-warp reduction)
    #pragma unroll
    for (int i = 0; i < 4; i++) {
        float mx = -1e30f;
        #pragma unroll
        for (int j = 0; j < 8; j++) mx = fmaxf(mx, acc[i][j]);
        #pragma unroll
        for (int o = 16; o > 0; o >>= 1) mx = fmaxf(mx, __shfl_xor_sync(0xffffffffu, mx, o));
        float s = 0.f;
        #pragma unroll
        for (int j = 0; j < 8; j++) {
            float e = __expf(10.0f * (acc[i][j] - mx));
            acc[i][j] = e; s += e;
        }
        #pragma unroll
        for (int o = 16; o > 0; o >>= 1) s += __shfl_xor_sync(0xffffffffu, s, o);
        float inv = 1.0f / s;
        float* orow = &d_attn[b][m0 + rg * 4 + i][0];
        #pragma unroll
        for (int j = 0; j < 8; j++) orow[lane + 32 * j] = acc[i][j] * inv;
    }
}

// ---------------------------------------------------------------------------
// Kernel 5: A' 9-tap shifted accumulation of attn.
// ---------------------------------------------------------------------------
__global__ __launch_bounds__(256) void k_aprime()
{
    int idx = blockIdx.x * 256 + threadIdx.x;   // NB*4096*256 total
    int n = idx & 255;
    int m = (idx >> 8) & 4095;
    int b = idx >> 20;
    int a = m >> 6, bb = m & 63, mh = n >> 4, mw = n & 15;
    float s = 0.f;
    #pragma unroll
    for (int di = -1; di <= 1; di++) {
        int a2 = a - di, mh2 = mh - di;
        if ((unsigned)a2 < 64u && (unsigned)mh2 < 16u) {
            #pragma unroll
            for (int dj = -1; dj <= 1; dj++) {
                int b2 = bb - dj, mw2 = mw - dj;
                if ((unsigned)b2 < 64u && (unsigned)mw2 < 16u)
                    s += d_attn[b][a2 * 64 + b2][mh2 * 16 + mw2];
            }
        }
    }
    d_Ap[b][m][n] = s;
}

// ---------------------------------------------------------------------------
// Kernel 6: final GEMM per batch: [4096 x 256] @ [256 x 1024], epilogue
// scatters to y[4a+r, 4b+q, co] with /6. Classic 128x128x8 SGEMM, 8x8/thread.
// ---------------------------------------------------------------------------
__global__ __launch_bounds__(256, 2) void k_final(float* __restrict__ out)
{
    int b = blockIdx.z;
    int m0 = blockIdx.y << 7;
    int n0 = blockIdx.x << 7;
    __shared__ float As[8][128];
    __shared__ float Bs[8][128];
    int t = threadIdx.x;
    int tx = t & 15, ty = t >> 4;
    const float* A  = &d_Ap[b][0][0];
    const float* Bg = &d_G[b][0][0];
    int arow = t >> 1, ac4 = (t & 1) << 2;
    int brow = t >> 5, bc4 = (t & 31) << 2;
    float acc[8][8];
    #pragma unroll
    for (int i = 0; i < 8; i++)
        #pragma unroll
        for (int j = 0; j < 8; j++) acc[i][j] = 0.f;

    for (int k0 = 0; k0 < 256; k0 += 8) {
        float4 av = *(const float4*)&A[(m0 + arow) * 256 + k0 + ac4];
        As[ac4 + 0][arow] = av.x;
        As[ac4 + 1][arow] = av.y;
        As[ac4 + 2][arow] = av.z;
        As[ac4 + 3][arow] = av.w;
        *(float4*)&Bs[brow][bc4] = *(const float4*)&Bg[(k0 + brow) * 1024 + n0 + bc4];
        __syncthreads();
        #pragma unroll
        for (int kk = 0; kk < 8; kk++) {
            float ar[8], br[8];
            *(float4*)&ar[0] = *(float4*)&As[kk][ty * 8];
            *(float4*)&ar[4] = *(float4*)&As[kk][ty * 8 + 4];
            *(float4*)&br[0] = *(float4*)&Bs[kk][tx * 8];
            *(float4*)&br[4] = *(float4*)&Bs[kk][tx * 8 + 4];
            #pragma unroll
            for (int i = 0; i < 8; i++)
                #pragma unroll
                for (int j = 0; j < 8; j++)
                    acc[i][j] = fmaf(ar[i], br[j], acc[i][j]);
        }
        __syncthreads();
    }

    const float inv6 = 1.0f / 6.0f;
    float* ob = out + (size_t)b * (256 * 256 * 64);
    #pragma unroll
    for (int i = 0; i < 8; i++) {
        int m = m0 + ty * 8 + i;
        int a = m >> 6, bw = m & 63;
        #pragma unroll
        for (int j4 = 0; j4 < 8; j4 += 4) {
            int j = n0 + tx * 8 + j4;
            int r = j >> 8, q = (j >> 6) & 3, co = j & 63;
            float4 v;
            v.x = acc[i][j4 + 0] * inv6;
            v.y = acc[i][j4 + 1] * inv6;
            v.z = acc[i][j4 + 2] * inv6;
            v.w = acc[i][j4 + 3] * inv6;
            *(float4*)&ob[(((a * 4 + r) * 256) + (bw * 4 + q)) * 64 + co] = v;
        }
    }
}

// ---------------------------------------------------------------------------
extern "C" void kernel_launch(void* const* d_in, const int* in_sizes, int n_in,
                              void* d_out, int out_size)
{
    const float* x  = (const float*)d_in[0];
    const float* tw = (const float*)d_in[1];
    const float* tb = (const float*)d_in[2];
    const float* ta = (const float*)d_in[3];
    const float* pw = (const float*)d_in[4];
    const float* pb = (const float*)d_in[5];
    const float* pa = (const float*)d_in[6];
    const float* gw = (const float*)d_in[7];
    const float* gb = (const float*)d_in[8];
    const float* ga = (const float*)d_in[9];
    float* out = (float*)d_out;

    k_theta_g<<<NB * 64, 256>>>(x, tw, tb, ta, gw, gb, ga);
    k_phi<<<NB, 256>>>(x, pw, pb, pa);
    k_phin<<<256, 256>>>();
    k_scores<<<dim3(128, NB), 256>>>();
    k_aprime<<<NB * 4096, 256>>>();
    k_final<<<dim3(8, 32, NB), 256>>>(out);
}

// round 4
// speedup vs baseline: 1.0516x; 1.0516x over previous
#include <cuda_runtime.h>
#include <math.h>

// ---------------------------------------------------------------------------
// CrossScaleNonLocalAttention  (B=8, H=W=64, C=64, CI=32, SCALE=4, PATCH=3)
//
// Same restructured math as R1; this round converts both GEMM mainloops to
// packed fp32x2 FMA (fma.rn.f32x2, sm_100+ only, never emitted by ptxas from
// C++), doubling the FP32 datapath throughput (~36 -> ~72 TF/s ceiling).
// ---------------------------------------------------------------------------

#define NB 8

__device__ float d_theta[NB][66][66][32];   // zero-padded border (never written)
__device__ float d_phi[NB][18][18][32];     // zero-padded border
__device__ float d_phin[NB][288][256];      // [k][n]  K-major for GEMM B
__device__ float d_G[NB][256][1024];        // G[(mh,mw)][(r*4+q)*64+co] = g(4mh+r,4mw+q,co)
__device__ float d_attn[NB][4096][256];
__device__ float d_Ap[NB][4096][256];

// ---- packed f32x2 helpers --------------------------------------------------
__device__ __forceinline__ unsigned long long dup2(float v) {
    unsigned long long r;
    asm("mov.b64 %0, {%1, %1};" : "=l"(r) : "f"(v));
    return r;
}
__device__ __forceinline__ void fma2(unsigned long long& d, unsigned long long a,
                                     unsigned long long b) {
    asm("fma.rn.f32x2 %0, %1, %2, %0;" : "+l"(d) : "l"(a), "l"(b));
}
__device__ __forceinline__ float2 unpack2(unsigned long long v) {
    float2 f;
    asm("mov.b64 {%0, %1}, %2;" : "=f"(f.x), "=f"(f.y) : "l"(v));
    return f;
}

// ---------------------------------------------------------------------------
// Kernel 1: theta (64->32) and g (64->64) 1x1 conv + PReLU, fused.
// ---------------------------------------------------------------------------
__global__ __launch_bounds__(256) void k_theta_g(
    const float* __restrict__ x,
    const float* __restrict__ tw, const float* __restrict__ tb, const float* __restrict__ ta,
    const float* __restrict__ gw, const float* __restrict__ gb, const float* __restrict__ ga)
{
    int b = blockIdx.x >> 6, h = blockIdx.x & 63;
    __shared__ float xs[64 * 64];
    __shared__ float tws[64 * 32];
    __shared__ float gws[64 * 64];
    __shared__ float tbs[32], tas[32], gbs[64], gas[64];
    int t = threadIdx.x;
    for (int i = t; i < 64 * 32; i += 256) tws[i] = tw[i];
    for (int i = t; i < 64 * 64; i += 256) gws[i] = gw[i];
    if (t < 32) { tbs[t] = tb[t]; tas[t] = ta[t]; }
    if (t < 64) { gbs[t] = gb[t]; gas[t] = ga[t]; }
    const float* xrow = x + ((size_t)(b * 4096 + h * 64)) * 64;
    for (int i = t * 4; i < 4096; i += 1024)
        *(float4*)&xs[i] = *(const float4*)&xrow[i];
    __syncthreads();

    int px = t >> 2, l4 = t & 3;
    {
        float acc[8];
        int d0 = l4 * 8;
        #pragma unroll
        for (int j = 0; j < 8; j++) acc[j] = tbs[d0 + j];
        #pragma unroll 8
        for (int c = 0; c < 64; c++) {
            float xv = xs[px * 64 + c];
            #pragma unroll
            for (int j = 0; j < 8; j++) acc[j] = fmaf(xv, tws[c * 32 + d0 + j], acc[j]);
        }
        float* o = &d_theta[b][h + 1][px + 1][d0];
        #pragma unroll
        for (int j = 0; j < 8; j++) { float v = acc[j]; o[j] = v >= 0.f ? v : tas[d0 + j] * v; }
    }
    {
        float acc[16];
        int d0 = l4 * 16;
        #pragma unroll
        for (int j = 0; j < 16; j++) acc[j] = gbs[d0 + j];
        #pragma unroll 8
        for (int c = 0; c < 64; c++) {
            float xv = xs[px * 64 + c];
            #pragma unroll
            for (int j = 0; j < 16; j++) acc[j] = fmaf(xv, gws[c * 64 + d0 + j], acc[j]);
        }
        int mh = h >> 2, r = h & 3, mw = px >> 2, q = px & 3;
        float* o = &d_G[b][mh * 16 + mw][((r * 4 + q) << 6) + d0];
        #pragma unroll
        for (int j = 0; j < 16; j++) { float v = acc[j]; o[j] = v >= 0.f ? v : gas[d0 + j] * v; }
    }
}

// ---------------------------------------------------------------------------
// Kernel 2: phi = prelu(conv1x1(bilinear_down4(x))).
// ---------------------------------------------------------------------------
__global__ __launch_bounds__(256) void k_phi(
    const float* __restrict__ x,
    const float* __restrict__ pw, const float* __restrict__ pb, const float* __restrict__ pa)
{
    int b = blockIdx.x;
    int t = threadIdx.x;
    __shared__ float pws[64 * 32];
    __shared__ float pbs[32], pas[32];
    for (int i = t; i < 64 * 32; i += 256) pws[i] = pw[i];
    if (t < 32) { pbs[t] = pb[t]; pas[t] = pa[t]; }
    __syncthreads();
    int nh = t >> 4, nw = t & 15;
    const float* xb = x + (size_t)b * 4096 * 64;
    const float* r0 = xb + ((4 * nh + 1) * 64 + (4 * nw + 1)) * 64;
    const float* r1 = xb + ((4 * nh + 2) * 64 + (4 * nw + 1)) * 64;
    float acc[32];
    #pragma unroll
    for (int d = 0; d < 32; d++) acc[d] = pbs[d];
    for (int c = 0; c < 64; c++) {
        float xv = 0.25f * (r0[c] + r0[64 + c] + r1[c] + r1[64 + c]);
        #pragma unroll
        for (int d = 0; d < 32; d++) acc[d] = fmaf(xv, pws[c * 32 + d], acc[d]);
    }
    float* o = &d_phi[b][nh + 1][nw + 1][0];
    #pragma unroll
    for (int d = 0; d < 32; d++) { float v = acc[d]; o[d] = v >= 0.f ? v : pas[d] * v; }
}

// ---------------------------------------------------------------------------
// Kernel 3: per-n patch L2 norm; write normalized patch rows K-major.
// ---------------------------------------------------------------------------
__global__ __launch_bounds__(256) void k_phin()
{
    int gwid = (blockIdx.x * 256 + threadIdx.x) >> 5;
    int lane = threadIdx.x & 31;
    if (gwid >= NB * 256) return;
    int b = gwid >> 8, n = gwid & 255;
    int nh = n >> 4, nw = n & 15;
    float v[9], ss = 0.f;
    #pragma unroll
    for (int i = 0; i < 9; i++) {
        v[i] = d_phi[b][nh + i / 3][nw + i % 3][lane];
        ss = fmaf(v[i], v[i], ss);
    }
    #pragma unroll
    for (int o = 16; o > 0; o >>= 1) ss += __shfl_xor_sync(0xffffffffu, ss, o);
    float rn = 1.0f / fmaxf(sqrtf(ss), 1e-6f);
    #pragma unroll
    for (int i = 0; i < 9; i++) d_phin[b][i * 32 + lane][n] = v[i] * rn;
}

// ---------------------------------------------------------------------------
// Kernel 4: scores GEMM (M=4096, N=256, K=288) + fused softmax(*10).
// Tile 64 rows x 256 cols per block (one image row). Warp w owns rows
// 8w..8w+7; lane owns col pairs {2*lane + 64*j}. Mainloop in fma.rn.f32x2.
// ---------------------------------------------------------------------------
__global__ __launch_bounds__(256, 2) void k_scores()
{
    int b = blockIdx.y;
    int h = blockIdx.x;               // m0 = h*64, w0 = 0
    int m0 = h << 6;
    __shared__ float Asm[64][17];
    __shared__ float Bsm[16][256];
    int t = threadIdx.x;
    int wid = t >> 5, lane = t & 31;

    unsigned long long acc2[8][4];
    #pragma unroll
    for (int i = 0; i < 8; i++)
        #pragma unroll
        for (int j = 0; j < 4; j++) acc2[i][j] = 0ull;

    int kk_l = t & 15, wl0 = t >> 4;  // A-tile loader coords
    for (int chunk = 0; chunk < 18; chunk++) {
        int pq = chunk >> 1;
        int c0 = (chunk & 1) << 4;
        int p = pq / 3, q = pq - 3 * p;
        #pragma unroll
        for (int r = 0; r < 4; r++)
            Asm[wl0 + 16 * r][kk_l] = d_theta[b][h + p][wl0 + 16 * r + q][c0 + kk_l];
        #pragma unroll
        for (int kk = 0; kk < 16; kk++)
            Bsm[kk][t] = d_phin[b][chunk * 16 + kk][t];
        __syncthreads();
        #pragma unroll
        for (int kk = 0; kk < 16; kk++) {
            unsigned long long avp[8], bv2[4];
            #pragma unroll
            for (int j = 0; j < 4; j++)
                bv2[j] = *(const unsigned long long*)&Bsm[kk][2 * lane + 64 * j];
            #pragma unroll
            for (int i = 0; i < 8; i++) avp[i] = dup2(Asm[wid * 8 + i][kk]);
            #pragma unroll
            for (int i = 0; i < 8; i++)
                #pragma unroll
                for (int j = 0; j < 4; j++)
                    fma2(acc2[i][j], avp[i], bv2[j]);
        }
        __syncthreads();
    }
    // fused softmax over 256 cols of each row (full-warp reduction)
    #pragma unroll
    for (int i = 0; i < 8; i++) {
        float e[8];
        #pragma unroll
        for (int j = 0; j < 4; j++) {
            float2 u = unpack2(acc2[i][j]);
            e[2 * j] = u.x; e[2 * j + 1] = u.y;
        }
        float mx = -1e30f;
        #pragma unroll
        for (int j = 0; j < 8; j++) mx = fmaxf(mx, e[j]);
        #pragma unroll
        for (int o = 16; o > 0; o >>= 1) mx = fmaxf(mx, __shfl_xor_sync(0xffffffffu, mx, o));
        float s = 0.f;
        #pragma unroll
        for (int j = 0; j < 8; j++) {
            float ev = __expf(10.0f * (e[j] - mx));
            e[j] = ev; s += ev;
        }
        #pragma unroll
        for (int o = 16; o > 0; o >>= 1) s += __shfl_xor_sync(0xffffffffu, s, o);
        float inv = 1.0f / s;
        float* orow = &d_attn[b][m0 + wid * 8 + i][0];
        #pragma unroll
        for (int j = 0; j < 4; j++) {
            float2 v; v.x = e[2 * j] * inv; v.y = e[2 * j + 1] * inv;
            *(float2*)&orow[2 * lane + 64 * j] = v;
        }
    }
}

// ---------------------------------------------------------------------------
// Kernel 5: A' 9-tap shifted accumulation of attn.
// ---------------------------------------------------------------------------
__global__ __launch_bounds__(256) void k_aprime()
{
    int idx = blockIdx.x * 256 + threadIdx.x;   // NB*4096*256 total
    int n = idx & 255;
    int m = (idx >> 8) & 4095;
    int b = idx >> 20;
    int a = m >> 6, bb = m & 63, mh = n >> 4, mw = n & 15;
    float s = 0.f;
    #pragma unroll
    for (int di = -1; di <= 1; di++) {
        int a2 = a - di, mh2 = mh - di;
        if ((unsigned)a2 < 64u && (unsigned)mh2 < 16u) {
            #pragma unroll
            for (int dj = -1; dj <= 1; dj++) {
                int b2 = bb - dj, mw2 = mw - dj;
                if ((unsigned)b2 < 64u && (unsigned)mw2 < 16u)
                    s += d_attn[b][a2 * 64 + b2][mh2 * 16 + mw2];
            }
        }
    }
    d_Ap[b][m][n] = s;
}

// ---------------------------------------------------------------------------
// Kernel 6: final GEMM per batch: [4096 x 256] @ [256 x 1024], 128x128x8
// tiles, 8x8 per thread, mainloop in fma.rn.f32x2 (accumulators packed along
// N pairs). Epilogue scatters to y[4a+r, 4b+q, co] with /6.
// ---------------------------------------------------------------------------
__global__ __launch_bounds__(256, 2) void k_final(float* __restrict__ out)
{
    int b = blockIdx.z;
    int m0 = blockIdx.y << 7;
    int n0 = blockIdx.x << 7;
    __shared__ float As[8][128];
    __shared__ float Bs[8][128];
    int t = threadIdx.x;
    int tx = t & 15, ty = t >> 4;
    const float* A  = &d_Ap[b][0][0];
    const float* Bg = &d_G[b][0][0];
    int arow = t >> 1, ac4 = (t & 1) << 2;
    int brow = t >> 5, bc4 = (t & 31) << 2;

    unsigned long long acc2[8][4];
    #pragma unroll
    for (int i = 0; i < 8; i++)
        #pragma unroll
        for (int j = 0; j < 4; j++) acc2[i][j] = 0ull;

    for (int k0 = 0; k0 < 256; k0 += 8) {
        float4 av = *(const float4*)&A[(m0 + arow) * 256 + k0 + ac4];
        As[ac4 + 0][arow] = av.x;
        As[ac4 + 1][arow] = av.y;
        As[ac4 + 2][arow] = av.z;
        As[ac4 + 3][arow] = av.w;
        *(float4*)&Bs[brow][bc4] = *(const float4*)&Bg[(k0 + brow) * 1024 + n0 + bc4];
        __syncthreads();
        #pragma unroll
        for (int kk = 0; kk < 8; kk++) {
            float ar[8];
            unsigned long long arp[8], br2[4];
            *(float4*)&ar[0] = *(float4*)&As[kk][ty * 8];
            *(float4*)&ar[4] = *(float4*)&As[kk][ty * 8 + 4];
            #pragma unroll
            for (int j = 0; j < 4; j++)
                br2[j] = *(const unsigned long long*)&Bs[kk][tx * 8 + 2 * j];
            #pragma unroll
            for (int i = 0; i < 8; i++) arp[i] = dup2(ar[i]);
            #pragma unroll
            for (int i = 0; i < 8; i++)
                #pragma unroll
                for (int j = 0; j < 4; j++)
                    fma2(acc2[i][j], arp[i], br2[j]);
        }
        __syncthreads();
    }

    const float inv6 = 1.0f / 6.0f;
    float* ob = out + (size_t)b * (256 * 256 * 64);
    #pragma unroll
    for (int i = 0; i < 8; i++) {
        int m = m0 + ty * 8 + i;
        int a = m >> 6, bw = m & 63;
        #pragma unroll
        for (int jh = 0; jh < 2; jh++) {     // two float4 stores (cols 0-3, 4-7)
            int j = n0 + tx * 8 + jh * 4;
            int r = j >> 8, q = (j >> 6) & 3, co = j & 63;
            float2 u0 = unpack2(acc2[i][jh * 2 + 0]);
            float2 u1 = unpack2(acc2[i][jh * 2 + 1]);
            float4 v;
            v.x = u0.x * inv6; v.y = u0.y * inv6;
            v.z = u1.x * inv6; v.w = u1.y * inv6;
            *(float4*)&ob[(((a * 4 + r) * 256) + (bw * 4 + q)) * 64 + co] = v;
        }
    }
}

// ---------------------------------------------------------------------------
extern "C" void kernel_launch(void* const* d_in, const int* in_sizes, int n_in,
                              void* d_out, int out_size)
{
    const float* x  = (const float*)d_in[0];
    const float* tw = (const float*)d_in[1];
    const float* tb = (const float*)d_in[2];
    const float* ta = (const float*)d_in[3];
    const float* pw = (const float*)d_in[4];
    const float* pb = (const float*)d_in[5];
    const float* pa = (const float*)d_in[6];
    const float* gw = (const float*)d_in[7];
    const float* gb = (const float*)d_in[8];
    const float* ga = (const float*)d_in[9];
    float* out = (float*)d_out;

    k_theta_g<<<NB * 64, 256>>>(x, tw, tb, ta, gw, gb, ga);
    k_phi<<<NB, 256>>>(x, pw, pb, pa);
    k_phin<<<256, 256>>>();
    k_scores<<<dim3(64, NB), 256>>>();
    k_aprime<<<NB * 4096, 256>>>();
    k_final<<<dim3(8, 32, NB), 256>>>(out);
}

// round 7
// speedup vs baseline: 1.5411x; 1.4655x over previous
#include <cuda_runtime.h>
#include <cuda_bf16.h>
#include <math.h>
#include <stdint.h>

// ---------------------------------------------------------------------------
// CrossScaleNonLocalAttention  (B=8, H=W=64, C=64, CI=32, SCALE=4, PATCH=3)
//
// R6: tcgen05 is unavailable (harness builds via compute_103 virtual arch, so
// 'a'-suffix features are rejected by ptxas). Final GEMM instead uses the
// baseline tensor-core path: mma.sync.m16n8k16 bf16 with hi/lo split (3
// products ~ fp32 precision) + ldmatrix. Producers emit bf16 hi/lo operands
// (Ap from k_aprime, Gt transposed from k_theta_g).
// ---------------------------------------------------------------------------

#define NB 8

__device__ float d_theta[NB][66][66][32];           // zero-padded border
__device__ float d_phi[NB][18][18][32];             // zero-padded border
__device__ float d_phin[NB][288][256];              // [k][n] K-major
__device__ float d_attn[NB][4096][256];
__device__ __nv_bfloat16 d_Ap_h[NB][4096][256];     // A' hi/lo split
__device__ __nv_bfloat16 d_Ap_l[NB][4096][256];
__device__ __nv_bfloat16 d_Gt_h[NB][1024][256];     // Gt[n][k] hi/lo split
__device__ __nv_bfloat16 d_Gt_l[NB][1024][256];

// ---- packed f32x2 helpers (k_scores) ---------------------------------------
__device__ __forceinline__ unsigned long long dup2(float v) {
    unsigned long long r;
    asm("mov.b64 %0, {%1, %1};" : "=l"(r) : "f"(v));
    return r;
}
__device__ __forceinline__ void fma2(unsigned long long& d, unsigned long long a,
                                     unsigned long long b) {
    asm("fma.rn.f32x2 %0, %1, %2, %0;" : "+l"(d) : "l"(a), "l"(b));
}
__device__ __forceinline__ float2 unpack2(unsigned long long v) {
    float2 f;
    asm("mov.b64 {%0, %1}, %2;" : "=f"(f.x), "=f"(f.y) : "l"(v));
    return f;
}

// ---- mma.sync helpers ------------------------------------------------------
__device__ __forceinline__ uint32_t smem_to_u32(const void* p) {
    uint32_t a;
    asm("{ .reg .u64 tmp; cvta.to.shared.u64 tmp, %1; cvt.u32.u64 %0, tmp; }"
        : "=r"(a) : "l"(p));
    return a;
}
__device__ __forceinline__ void ldsm_x4(uint32_t* r, uint32_t addr) {
    asm volatile("ldmatrix.sync.aligned.m8n8.x4.shared.b16 {%0,%1,%2,%3}, [%4];"
                 : "=r"(r[0]), "=r"(r[1]), "=r"(r[2]), "=r"(r[3]) : "r"(addr));
}
__device__ __forceinline__ void mma_bf16(float* d, const uint32_t* a, const uint32_t* b) {
    asm volatile(
        "mma.sync.aligned.m16n8k16.row.col.f32.bf16.bf16.f32 "
        "{%0,%1,%2,%3}, {%4,%5,%6,%7}, {%8,%9}, {%0,%1,%2,%3};"
        : "+f"(d[0]), "+f"(d[1]), "+f"(d[2]), "+f"(d[3])
        : "r"(a[0]), "r"(a[1]), "r"(a[2]), "r"(a[3]), "r"(b[0]), "r"(b[1]));
}

// ---------------------------------------------------------------------------
// Kernel 1: theta (64->32) and g (64->64) 1x1 conv + PReLU, fused.
// g outputs are transposed through SMEM and stored as Gt[n][k] bf16 hi/lo,
// where n=(r*4+q)*64+co, k=mh*16+mw  (final-GEMM B operand, K-major).
// ---------------------------------------------------------------------------
__global__ __launch_bounds__(256) void k_theta_g(
    const float* __restrict__ x,
    const float* __restrict__ tw, const float* __restrict__ tb, const float* __restrict__ ta,
    const float* __restrict__ gw, const float* __restrict__ gb, const float* __restrict__ ga)
{
    int b = blockIdx.x >> 6, h = blockIdx.x & 63;
    __shared__ float xs[64 * 64];
    __shared__ float tws[64 * 32];
    __shared__ float gws[64 * 64];
    __shared__ float tbs[32], tas[32], gbs[64], gas[64];
    int t = threadIdx.x;
    for (int i = t; i < 64 * 32; i += 256) tws[i] = tw[i];
    for (int i = t; i < 64 * 64; i += 256) gws[i] = gw[i];
    if (t < 32) { tbs[t] = tb[t]; tas[t] = ta[t]; }
    if (t < 64) { gbs[t] = gb[t]; gas[t] = ga[t]; }
    const float* xrow = x + ((size_t)(b * 4096 + h * 64)) * 64;
    for (int i = t * 4; i < 4096; i += 1024)
        *(float4*)&xs[i] = *(const float4*)&xrow[i];
    __syncthreads();

    int px = t >> 2, l4 = t & 3;
    // theta: 8 outputs per thread
    {
        float acc[8];
        int d0 = l4 * 8;
        #pragma unroll
        for (int j = 0; j < 8; j++) acc[j] = tbs[d0 + j];
        #pragma unroll 8
        for (int c = 0; c < 64; c++) {
            float xv = xs[px * 64 + c];
            #pragma unroll
            for (int j = 0; j < 8; j++) acc[j] = fmaf(xv, tws[c * 32 + d0 + j], acc[j]);
        }
        float* o = &d_theta[b][h + 1][px + 1][d0];
        #pragma unroll
        for (int j = 0; j < 8; j++) { float v = acc[j]; o[j] = v >= 0.f ? v : tas[d0 + j] * v; }
    }
    // g: 16 outputs per thread
    float gacc[16];
    {
        int d0 = l4 * 16;
        #pragma unroll
        for (int j = 0; j < 16; j++) gacc[j] = gbs[d0 + j];
        #pragma unroll 8
        for (int c = 0; c < 64; c++) {
            float xv = xs[px * 64 + c];
            #pragma unroll
            for (int j = 0; j < 16; j++) gacc[j] = fmaf(xv, gws[c * 64 + d0 + j], gacc[j]);
        }
        #pragma unroll
        for (int j = 0; j < 16; j++) {
            float v = gacc[j];
            gacc[j] = v >= 0.f ? v : gas[d0 + j] * v;
        }
    }
    __syncthreads();           // all xs reads done; reuse xs for g staging
    {
        int d0 = l4 * 16;
        #pragma unroll
        for (int j = 0; j < 16; j++) xs[px * 64 + d0 + j] = gacc[j];
    }
    __syncthreads();
    // transpose-write: thread t -> (q = t>>6, ch = t&63); 16 k-values (mw 0..15)
    {
        int q = t >> 6, ch = t & 63;
        int mh = h >> 2, r = h & 3;
        __nv_bfloat16 hi[16], lo[16];
        #pragma unroll
        for (int mw = 0; mw < 16; mw++) {
            float v = xs[(mw * 4 + q) * 64 + ch];
            __nv_bfloat16 hb = __float2bfloat16(v);
            hi[mw] = hb;
            lo[mw] = __float2bfloat16(v - __bfloat162float(hb));
        }
        int n = (r * 4 + q) * 64 + ch;
        uint4* dh = (uint4*)&d_Gt_h[b][n][mh * 16];
        uint4* dl = (uint4*)&d_Gt_l[b][n][mh * 16];
        dh[0] = ((uint4*)hi)[0]; dh[1] = ((uint4*)hi)[1];
        dl[0] = ((uint4*)lo)[0]; dl[1] = ((uint4*)lo)[1];
    }
}

// ---------------------------------------------------------------------------
// Kernel 2: phi = prelu(conv1x1(bilinear_down4(x))).
// ---------------------------------------------------------------------------
__global__ __launch_bounds__(256) void k_phi(
    const float* __restrict__ x,
    const float* __restrict__ pw, const float* __restrict__ pb, const float* __restrict__ pa)
{
    int b = blockIdx.x;
    int t = threadIdx.x;
    __shared__ float pws[64 * 32];
    __shared__ float pbs[32], pas[32];
    for (int i = t; i < 64 * 32; i += 256) pws[i] = pw[i];
    if (t < 32) { pbs[t] = pb[t]; pas[t] = pa[t]; }
    __syncthreads();
    int nh = t >> 4, nw = t & 15;
    const float* xb = x + (size_t)b * 4096 * 64;
    const float* r0 = xb + ((4 * nh + 1) * 64 + (4 * nw + 1)) * 64;
    const float* r1 = xb + ((4 * nh + 2) * 64 + (4 * nw + 1)) * 64;
    float acc[32];
    #pragma unroll
    for (int d = 0; d < 32; d++) acc[d] = pbs[d];
    for (int c = 0; c < 64; c++) {
        float xv = 0.25f * (r0[c] + r0[64 + c] + r1[c] + r1[64 + c]);
        #pragma unroll
        for (int d = 0; d < 32; d++) acc[d] = fmaf(xv, pws[c * 32 + d], acc[d]);
    }
    float* o = &d_phi[b][nh + 1][nw + 1][0];
    #pragma unroll
    for (int d = 0; d < 32; d++) { float v = acc[d]; o[d] = v >= 0.f ? v : pas[d] * v; }
}

// ---------------------------------------------------------------------------
// Kernel 3: per-n patch L2 norm; write normalized patch rows K-major.
// ---------------------------------------------------------------------------
__global__ __launch_bounds__(256) void k_phin()
{
    int gwid = (blockIdx.x * 256 + threadIdx.x) >> 5;
    int lane = threadIdx.x & 31;
    if (gwid >= NB * 256) return;
    int b = gwid >> 8, n = gwid & 255;
    int nh = n >> 4, nw = n & 15;
    float v[9], ss = 0.f;
    #pragma unroll
    for (int i = 0; i < 9; i++) {
        v[i] = d_phi[b][nh + i / 3][nw + i % 3][lane];
        ss = fmaf(v[i], v[i], ss);
    }
    #pragma unroll
    for (int o = 16; o > 0; o >>= 1) ss += __shfl_xor_sync(0xffffffffu, ss, o);
    float rn = 1.0f / fmaxf(sqrtf(ss), 1e-6f);
    #pragma unroll
    for (int i = 0; i < 9; i++) d_phin[b][i * 32 + lane][n] = v[i] * rn;
}

// ---------------------------------------------------------------------------
// Kernel 4: scores GEMM (M=4096, N=256, K=288) + fused softmax(*10). fp32.
// ---------------------------------------------------------------------------
__global__ __launch_bounds__(256, 2) void k_scores()
{
    int b = blockIdx.y;
    int h = blockIdx.x;               // m0 = h*64
    int m0 = h << 6;
    __shared__ float Asm[64][17];
    __shared__ float Bsm[16][256];
    int t = threadIdx.x;
    int wid = t >> 5, lane = t & 31;

    unsigned long long acc2[8][4];
    #pragma unroll
    for (int i = 0; i < 8; i++)
        #pragma unroll
        for (int j = 0; j < 4; j++) acc2[i][j] = 0ull;

    int kk_l = t & 15, wl0 = t >> 4;
    for (int chunk = 0; chunk < 18; chunk++) {
        int pq = chunk >> 1;
        int c0 = (chunk & 1) << 4;
        int p = pq / 3, q = pq - 3 * p;
        #pragma unroll
        for (int r = 0; r < 4; r++)
            Asm[wl0 + 16 * r][kk_l] = d_theta[b][h + p][wl0 + 16 * r + q][c0 + kk_l];
        #pragma unroll
        for (int kk = 0; kk < 16; kk++)
            Bsm[kk][t] = d_phin[b][chunk * 16 + kk][t];
        __syncthreads();
        #pragma unroll
        for (int kk = 0; kk < 16; kk++) {
            unsigned long long avp[8], bv2[4];
            #pragma unroll
            for (int j = 0; j < 4; j++)
                bv2[j] = *(const unsigned long long*)&Bsm[kk][2 * lane + 64 * j];
            #pragma unroll
            for (int i = 0; i < 8; i++) avp[i] = dup2(Asm[wid * 8 + i][kk]);
            #pragma unroll
            for (int i = 0; i < 8; i++)
                #pragma unroll
                for (int j = 0; j < 4; j++)
                    fma2(acc2[i][j], avp[i], bv2[j]);
        }
        __syncthreads();
    }
    #pragma unroll
    for (int i = 0; i < 8; i++) {
        float e[8];
        #pragma unroll
        for (int j = 0; j < 4; j++) {
            float2 u = unpack2(acc2[i][j]);
            e[2 * j] = u.x; e[2 * j + 1] = u.y;
        }
        float mx = -1e30f;
        #pragma unroll
        for (int j = 0; j < 8; j++) mx = fmaxf(mx, e[j]);
        #pragma unroll
        for (int o = 16; o > 0; o >>= 1) mx = fmaxf(mx, __shfl_xor_sync(0xffffffffu, mx, o));
        float s = 0.f;
        #pragma unroll
        for (int j = 0; j < 8; j++) {
            float ev = __expf(10.0f * (e[j] - mx));
            e[j] = ev; s += ev;
        }
        #pragma unroll
        for (int o = 16; o > 0; o >>= 1) s += __shfl_xor_sync(0xffffffffu, s, o);
        float inv = 1.0f / s;
        float* orow = &d_attn[b][m0 + wid * 8 + i][0];
        #pragma unroll
        for (int j = 0; j < 4; j++) {
            float2 v; v.x = e[2 * j] * inv; v.y = e[2 * j + 1] * inv;
            *(float2*)&orow[2 * lane + 64 * j] = v;
        }
    }
}

// ---------------------------------------------------------------------------
// Kernel 5: A' 9-tap shifted accumulation of attn -> bf16 hi/lo split.
// ---------------------------------------------------------------------------
__global__ __launch_bounds__(256) void k_aprime()
{
    int idx = blockIdx.x * 256 + threadIdx.x;   // NB*4096*256 total
    int n = idx & 255;
    int m = (idx >> 8) & 4095;
    int b = idx >> 20;
    int a = m >> 6, bb = m & 63, mh = n >> 4, mw = n & 15;
    float s = 0.f;
    #pragma unroll
    for (int di = -1; di <= 1; di++) {
        int a2 = a - di, mh2 = mh - di;
        if ((unsigned)a2 < 64u && (unsigned)mh2 < 16u) {
            #pragma unroll
            for (int dj = -1; dj <= 1; dj++) {
                int b2 = bb - dj, mw2 = mw - dj;
                if ((unsigned)b2 < 64u && (unsigned)mw2 < 16u)
                    s += d_attn[b][a2 * 64 + b2][mh2 * 16 + mw2];
            }
        }
    }
    __nv_bfloat16 hb = __float2bfloat16(s);
    d_Ap_h[b][m][n] = hb;
    d_Ap_l[b][m][n] = __float2bfloat16(s - __bfloat162float(hb));
}

// ---------------------------------------------------------------------------
// Kernel 6: final GEMM via mma.sync bf16 hi/lo split.
// Per CTA: D[128m x 128n] = Ap[128 x 256k] @ Gt[128n x 256k]^T.
// 8 warps (4m x 2n), warp tile 32m x 64n (2 m-frags x 8 n-frags of m16n8k16).
// K-chunks of 32 in SMEM with 80B-padded rows (conflict-free ldmatrix).
// Epilogue scatters float2 pairs to y[4a+r, 4b+q, co] with /6.
// ---------------------------------------------------------------------------
#define KF_RS   80                    // padded row stride (64B data + 16B pad)
#define KF_AH   0
#define KF_AL   10240
#define KF_BH   20480
#define KF_BL   30720

__global__ __launch_bounds__(256) void k_final_mma(float* __restrict__ out)
{
    __shared__ __align__(16) char sm[40960];
    int t = threadIdx.x, lane = t & 31, wid = t >> 5;
    int b = blockIdx.z, m0 = blockIdx.y << 7, n0 = blockIdx.x << 7;
    int wm = wid >> 1, wn = wid & 1;
    uint32_t sbase = smem_to_u32(sm);

    float acc[2][8][4];
    #pragma unroll
    for (int i = 0; i < 2; i++)
        #pragma unroll
        for (int j = 0; j < 8; j++)
            #pragma unroll
            for (int k = 0; k < 4; k++) acc[i][j][k] = 0.f;

    for (int kc = 0; kc < 8; kc++) {
        int k0 = kc << 5;
        if (kc) __syncthreads();
        #pragma unroll
        for (int i = 0; i < 2; i++) {
            int idx = t + (i << 8);        // 0..511
            int row = idx >> 2, seg = idx & 3;
            int so = row * KF_RS + seg * 16;
            int gk = k0 + seg * 8;
            *(uint4*)(sm + KF_AH + so) = *(const uint4*)&d_Ap_h[b][m0 + row][gk];
            *(uint4*)(sm + KF_AL + so) = *(const uint4*)&d_Ap_l[b][m0 + row][gk];
            *(uint4*)(sm + KF_BH + so) = *(const uint4*)&d_Gt_h[b][n0 + row][gk];
            *(uint4*)(sm + KF_BL + so) = *(const uint4*)&d_Gt_l[b][n0 + row][gk];
        }
        __syncthreads();
        int lrow = lane & 15, lcol = (lane >> 4) << 4;
        #pragma unroll
        for (int ks = 0; ks < 2; ks++) {
            int colo = ks * 32 + lcol;
            uint32_t ah[2][4], al[2][4], bh[8][2], bl[8][2];
            #pragma unroll
            for (int mf = 0; mf < 2; mf++) {
                uint32_t addr = sbase + (wm * 32 + mf * 16 + lrow) * KF_RS + colo;
                ldsm_x4(ah[mf], addr + KF_AH);
                ldsm_x4(al[mf], addr + KF_AL);
            }
            #pragma unroll
            for (int ng = 0; ng < 4; ng++) {
                uint32_t addr = sbase + (wn * 64 + ng * 16 + lrow) * KF_RS + colo;
                uint32_t r4[4];
                ldsm_x4(r4, addr + KF_BH);
                bh[ng * 2][0] = r4[0]; bh[ng * 2][1] = r4[2];
                bh[ng * 2 + 1][0] = r4[1]; bh[ng * 2 + 1][1] = r4[3];
                ldsm_x4(r4, addr + KF_BL);
                bl[ng * 2][0] = r4[0]; bl[ng * 2][1] = r4[2];
                bl[ng * 2 + 1][0] = r4[1]; bl[ng * 2 + 1][1] = r4[3];
            }
            #pragma unroll
            for (int mf = 0; mf < 2; mf++)
                #pragma unroll
                for (int nf = 0; nf < 8; nf++) {
                    mma_bf16(acc[mf][nf], ah[mf], bh[nf]);
                    mma_bf16(acc[mf][nf], ah[mf], bl[nf]);
                    mma_bf16(acc[mf][nf], al[mf], bh[nf]);
                }
        }
    }

    // epilogue: scatter with /6
    const float inv6 = 1.0f / 6.0f;
    int group = lane >> 2, tig = lane & 3;
    float* ob = out + (size_t)b * 4194304;
    #pragma unroll
    for (int mf = 0; mf < 2; mf++) {
        #pragma unroll
        for (int nf = 0; nf < 8; nf++) {
            int n = n0 + wn * 64 + nf * 8 + tig * 2;
            int r = n >> 8, q = (n >> 6) & 3, co = n & 63;
            #pragma unroll
            for (int half = 0; half < 2; half++) {
                int m = m0 + wm * 32 + mf * 16 + group + half * 8;
                int a = m >> 6, bw = m & 63;
                float2 v;
                v.x = acc[mf][nf][half * 2 + 0] * inv6;
                v.y = acc[mf][nf][half * 2 + 1] * inv6;
                *(float2*)&ob[((size_t)((a * 4 + r) * 256 + bw * 4 + q)) * 64 + co] = v;
            }
        }
    }
}

// ---------------------------------------------------------------------------
extern "C" void kernel_launch(void* const* d_in, const int* in_sizes, int n_in,
                              void* d_out, int out_size)
{
    const float* x  = (const float*)d_in[0];
    const float* tw = (const float*)d_in[1];
    const float* tb = (const float*)d_in[2];
    const float* ta = (const float*)d_in[3];
    const float* pw = (const float*)d_in[4];
    const float* pb = (const float*)d_in[5];
    const float* pa = (const float*)d_in[6];
    const float* gw = (const float*)d_in[7];
    const float* gb = (const float*)d_in[8];
    const float* ga = (const float*)d_in[9];
    float* out = (float*)d_out;

    k_theta_g<<<NB * 64, 256>>>(x, tw, tb, ta, gw, gb, ga);
    k_phi<<<NB, 256>>>(x, pw, pb, pa);
    k_phin<<<256, 256>>>();
    k_scores<<<dim3(64, NB), 256>>>();
    k_aprime<<<NB * 4096, 256>>>();
    k_final_mma<<<dim3(8, 32, NB), 256>>>(out);
}